// round 14
// baseline (speedup 1.0000x reference)
#include <cuda_runtime.h>

#define BB 4
#define LL 2048
#define EE 1024
#define HH 16
#define HD 64
#define MM (BB*LL)   // 8192

// Scratch (allocation-free), all tf32-encoded uints.
// g_X, g_Wc, g_A are stored K-PAIR-PERMUTED: each 8-element k-octet holds
// [L0,L4,L1,L5,L2,L6,L3,L7]. g_Q/g_K/g_V are natural (attention consumes).
__device__ unsigned g_Q[MM*EE];
__device__ unsigned g_K[MM*EE];
__device__ unsigned g_V[MM*EE];
__device__ unsigned g_A[MM*EE];
__device__ unsigned g_X[MM*EE];
__device__ unsigned g_Wc[4*EE*EE];
__device__ int g_idx[BB*LL];
__device__ int g_cnt[BB];

__device__ __forceinline__ unsigned f2tf32(float v) {
    unsigned u;
    asm("cvt.rna.tf32.f32 %0, %1;" : "=r"(u) : "f"(v));
    return u;
}

__device__ __forceinline__ void mma_tf32(float* c,
    unsigned a0, unsigned a1, unsigned a2, unsigned a3,
    unsigned b0, unsigned b1) {
    asm volatile(
        "mma.sync.aligned.m16n8k8.row.col.f32.tf32.tf32.f32 "
        "{%0,%1,%2,%3}, {%4,%5,%6,%7}, {%8,%9}, {%0,%1,%2,%3};\n"
        : "+f"(c[0]), "+f"(c[1]), "+f"(c[2]), "+f"(c[3])
        : "r"(a0), "r"(a1), "r"(a2), "r"(a3), "r"(b0), "r"(b1));
}

__device__ __forceinline__ void cp16(void* dst_smem, const void* src) {
    unsigned d = (unsigned)__cvta_generic_to_shared(dst_smem);
    asm volatile("cp.async.cg.shared.global [%0], [%1], 16;" :: "r"(d), "l"(src));
}

// fp32 -> tf32, K-PAIR-PERMUTED: out octet = [L0,L4,L1,L5,L2,L6,L3,L7]
__global__ void conv_tf32_perm_kernel(const float4* __restrict__ in,
                                      uint4* __restrict__ out, int n8) {
    int i = blockIdx.x * blockDim.x + threadIdx.x;   // octet index
    if (i < n8) {
        float4 a = in[2 * i];       // L0..L3
        float4 b = in[2 * i + 1];   // L4..L7
        out[2 * i]     = make_uint4(f2tf32(a.x), f2tf32(b.x), f2tf32(a.y), f2tf32(b.y));
        out[2 * i + 1] = make_uint4(f2tf32(a.z), f2tf32(b.z), f2tf32(a.w), f2tf32(b.w));
    }
}

// all 4 weights, permuted, one launch (grid.y selects weight)
__global__ void conv_w4_perm_kernel(const float4* __restrict__ w0, const float4* __restrict__ w1,
                                    const float4* __restrict__ w2, const float4* __restrict__ w3,
                                    uint4* __restrict__ out, int n8w) {
    const float4* src = (blockIdx.y == 0) ? w0 : (blockIdx.y == 1) ? w1
                      : (blockIdx.y == 2) ? w2 : w3;
    int i = blockIdx.x * blockDim.x + threadIdx.x;
    if (i < n8w) {
        float4 a = src[2 * i];
        float4 b = src[2 * i + 1];
        size_t o = (size_t)blockIdx.y * (2 * (size_t)n8w) + 2 * i;
        out[o]     = make_uint4(f2tf32(a.x), f2tf32(b.x), f2tf32(a.y), f2tf32(b.y));
        out[o + 1] = make_uint4(f2tf32(a.z), f2tf32(b.z), f2tf32(a.w), f2tf32(b.w));
    }
}

// ---------------------------------------------------------------------------
// Per-batch mask compaction: idx[b][0..cnt) = pseudo-positions with mask!=0.
// ---------------------------------------------------------------------------
__global__ __launch_bounds__(1024) void compact_mask_kernel(
    const int* __restrict__ mask, int* __restrict__ idx, int* __restrict__ cnt)
{
    __shared__ int wsum[32];
    int b = blockIdx.x, t = threadIdx.x;
    int lane = t & 31, w = t >> 5;

    int v0 = mask[b * LL + 2 * t];
    int v1 = mask[b * LL + 2 * t + 1];
    int n = (v0 != 0) + (v1 != 0);

    int s = n;
    #pragma unroll
    for (int d = 1; d < 32; d <<= 1) {
        int x = __shfl_up_sync(0xffffffffu, s, d);
        if (lane >= d) s += x;
    }
    if (lane == 31) wsum[w] = s;
    __syncthreads();
    if (w == 0) {
        int x = wsum[lane];
        #pragma unroll
        for (int d = 1; d < 32; d <<= 1) {
            int y = __shfl_up_sync(0xffffffffu, x, d);
            if (lane >= d) x += y;
        }
        wsum[lane] = x;
    }
    __syncthreads();

    int base = (w > 0 ? wsum[w - 1] : 0) + (s - n);
    int p = base;
    if (v0) idx[b * LL + p++] = 2 * t;
    if (v1) idx[b * LL + p++] = 2 * t + 1;
    if (t == 1023) cnt[b] = wsum[31];
}

// ---------------------------------------------------------------------------
// Shared TF32 TC GEMM body: 128x256 CTA tile, BK=32, 8 warps (2m x 4n),
// warp tile 64x64, cp.async 2-stage. Operands K-PAIR-PERMUTED -> fragment
// loads are LDS.64. Row pad 40 words: 8B-bank = (4r + cc) mod 16 per
// half-warp -> conflict-free LDS.64 (pad 36 was 2-way conflicted).
// ---------------------------------------------------------------------------
#define GPAD 40
#define GS_A (128*GPAD)
#define GS_B (256*GPAD)
#define GEMM_SMEM ((2*GS_A + 2*GS_B) * 4)   // 122880 B

template <int STORE_TF32>
__device__ __forceinline__ void gemm_body(
    const unsigned* __restrict__ A, const unsigned* __restrict__ W,
    const float* __restrict__ bias, void* __restrict__ Cout,
    float oscale, int m0, int n0, unsigned* sm)
{
    unsigned* As = sm;
    unsigned* Bs = sm + 2 * GS_A;

    int tid = threadIdx.x;
    int w = tid >> 5, lane = tid & 31;
    int wm = (w & 1) * 64, wn = (w >> 1) * 64;
    int r = lane >> 2, cc = lane & 3;

    const unsigned* Abase = A + (size_t)m0 * EE;
    const unsigned* Wbase = W + (size_t)n0 * EE;

    float acc[4][8][4];
    #pragma unroll
    for (int mi = 0; mi < 4; mi++)
        #pragma unroll
        for (int ni = 0; ni < 8; ni++)
            #pragma unroll
            for (int j = 0; j < 4; j++) acc[mi][ni][j] = 0.f;

    auto fill = [&](int s, int k0) {
        #pragma unroll
        for (int i = 0; i < 4; i++) {
            int lin = tid + i * 256;
            int rr = lin >> 3, kc = (lin & 7) << 2;
            cp16(&As[s * GS_A + rr * GPAD + kc], Abase + (size_t)rr * EE + k0 + kc);
        }
        #pragma unroll
        for (int i = 0; i < 8; i++) {
            int lin = tid + i * 256;
            int rr = lin >> 3, kc = (lin & 7) << 2;
            cp16(&Bs[s * GS_B + rr * GPAD + kc], Wbase + (size_t)rr * EE + k0 + kc);
        }
        asm volatile("cp.async.commit_group;");
    };

    fill(0, 0);
    for (int it = 0; it < EE / 32; it++) {
        int cur = it & 1;
        if (it + 1 < EE / 32) {
            fill(1 - cur, (it + 1) * 32);
            asm volatile("cp.async.wait_group 1;");
        } else {
            asm volatile("cp.async.wait_group 0;");
        }
        __syncthreads();

        const unsigned* Ac = &As[cur * GS_A];
        const unsigned* Bc = &Bs[cur * GS_B];
        #pragma unroll
        for (int kk = 0; kk < 32; kk += 8) {
            unsigned af[4][4], bf[8][2];
            #pragma unroll
            for (int mi = 0; mi < 4; mi++) {
                int mb = wm + mi * 16;
                uint2 p0 = *reinterpret_cast<const uint2*>(&Ac[(mb + r) * GPAD + kk + 2 * cc]);
                uint2 p1 = *reinterpret_cast<const uint2*>(&Ac[(mb + 8 + r) * GPAD + kk + 2 * cc]);
                af[mi][0] = p0.x; af[mi][1] = p1.x;
                af[mi][2] = p0.y; af[mi][3] = p1.y;
            }
            #pragma unroll
            for (int ni = 0; ni < 8; ni++) {
                int nb = wn + ni * 8 + r;
                uint2 q = *reinterpret_cast<const uint2*>(&Bc[nb * GPAD + kk + 2 * cc]);
                bf[ni][0] = q.x; bf[ni][1] = q.y;
            }
            #pragma unroll
            for (int mi = 0; mi < 4; mi++)
                #pragma unroll
                for (int ni = 0; ni < 8; ni++)
                    mma_tf32(acc[mi][ni], af[mi][0], af[mi][1], af[mi][2], af[mi][3],
                             bf[ni][0], bf[ni][1]);
        }
        __syncthreads();
    }

    #pragma unroll
    for (int mi = 0; mi < 4; mi++) {
        int m = m0 + wm + mi * 16 + r;
        #pragma unroll
        for (int ni = 0; ni < 8; ni++) {
            int n = n0 + wn + ni * 8 + cc * 2;
            float2 bv = *reinterpret_cast<const float2*>(&bias[n]);
            float o0 = (acc[mi][ni][0] + bv.x) * oscale;
            float o1 = (acc[mi][ni][1] + bv.y) * oscale;
            float o2 = (acc[mi][ni][2] + bv.x) * oscale;
            float o3 = (acc[mi][ni][3] + bv.y) * oscale;
            if (STORE_TF32) {
                unsigned* C = (unsigned*)Cout;
                *reinterpret_cast<uint2*>(&C[(size_t)m * EE + n]) =
                    make_uint2(f2tf32(o0), f2tf32(o1));
                *reinterpret_cast<uint2*>(&C[(size_t)(m + 8) * EE + n]) =
                    make_uint2(f2tf32(o2), f2tf32(o3));
            } else {
                float* C = (float*)Cout;
                *reinterpret_cast<float2*>(&C[(size_t)m * EE + n]) = make_float2(o0, o1);
                *reinterpret_cast<float2*>(&C[(size_t)(m + 8) * EE + n]) = make_float2(o2, o3);
            }
        }
    }
}

// Fused Q/K/V projection: grid.z selects weight/bias/output/oscale.
// Inputs permuted; outputs NATURAL (consumed by attention).
__global__ __launch_bounds__(256) void qkv_gemm_tc(
    const unsigned* __restrict__ A, const unsigned* __restrict__ Wall,
    const float* __restrict__ bq, const float* __restrict__ bk,
    const float* __restrict__ bv,
    unsigned* __restrict__ Qo, unsigned* __restrict__ Ko, unsigned* __restrict__ Vo)
{
    extern __shared__ unsigned sm[];
    int z = blockIdx.z;
    const unsigned* W = Wall + (size_t)z * EE * EE;
    const float* bias = (z == 0) ? bq : (z == 1) ? bk : bv;
    unsigned* C = (z == 0) ? Qo : (z == 1) ? Ko : Vo;
    float oscale = (z == 0) ? 0.125f : 1.0f;
    gemm_body<1>(A, W, bias, C, oscale, blockIdx.y * 128, blockIdx.x * 256, sm);
}

// O-projection (fp32 natural output); inputs permuted.
__global__ __launch_bounds__(256) void ogemm_tc(
    const unsigned* __restrict__ A, const unsigned* __restrict__ W,
    const float* __restrict__ bias, float* __restrict__ Cout)
{
    extern __shared__ unsigned sm[];
    gemm_body<0>(A, W, bias, Cout, 1.0f, blockIdx.y * 128, blockIdx.x * 256, sm);
}

// ---------------------------------------------------------------------------
// Tensor-core flash attention over compacted keys, double-buffered cp.async
// gather. Output write K-PAIR-PERMUTED per 8-col octet (feeds ogemm).
// ---------------------------------------------------------------------------
#define ATTN_SMEM ((8704*3 + 128) * 4)   // 104960 B

__global__ __launch_bounds__(128) void attn_tc(
    const unsigned* __restrict__ Q, const unsigned* __restrict__ K,
    const unsigned* __restrict__ V, const int* __restrict__ idxp,
    const int* __restrict__ cntp, unsigned* __restrict__ O)
{
    extern __shared__ unsigned smn[];
    unsigned (*Ks)[64][68] = (unsigned (*)[64][68])smn;
    unsigned (*Vs)[64][68] = (unsigned (*)[64][68])(smn + 8704);
    unsigned (*Ps)[68] = (unsigned (*)[68])(smn + 17408);
    int* krs = (int*)(smn + 26112);

    int b = blockIdx.z, h = blockIdx.y;
    int q0 = blockIdx.x * 128;
    int t = threadIdx.x, w = t >> 5, lane = t & 31;
    int r = lane >> 2, cc = lane & 3;
    size_t hbase = ((size_t)(b * HH + h)) * LL * HD;
    unsigned (*Pw)[68] = &Ps[w * 32];

    int cnt = cntp[b];
    int ntiles = (cnt + 63) >> 6;

    auto fillKV = [&](int s) {
        #pragma unroll
        for (int i = 0; i < 8; i++) {
            int lin = t + i * 128;
            int row = lin >> 4, chunk = lin & 15, c = chunk << 2;
            int g = krs[s * 64 + row];
            size_t rb = hbase + (size_t)g * HD + c;
            cp16(&Ks[s][row][c], K + rb);
            cp16(&Vs[s][row][c], V + rb);
        }
        asm volatile("cp.async.commit_group;");
    };

    {
        const uint4* Qg = (const uint4*)(Q + hbase + (size_t)(q0 + w * 32) * HD);
        #pragma unroll
        for (int i = 0; i < 16; i++) {
            int lin = lane + i * 32;
            int row = lin >> 4, c = (lin & 15) << 2;
            *reinterpret_cast<uint4*>(&Pw[row][c]) = Qg[lin];
        }
    }
    __syncwarp();
    unsigned qa[2][8][4];
    #pragma unroll
    for (int mi = 0; mi < 2; mi++)
        #pragma unroll
        for (int ks = 0; ks < 8; ks++) {
            qa[mi][ks][0] = Pw[mi * 16 + r][ks * 8 + cc];
            qa[mi][ks][1] = Pw[mi * 16 + 8 + r][ks * 8 + cc];
            qa[mi][ks][2] = Pw[mi * 16 + r][ks * 8 + cc + 4];
            qa[mi][ks][3] = Pw[mi * 16 + 8 + r][ks * 8 + cc + 4];
        }

    if (t < 64) krs[t] = (t < cnt) ? idxp[b * LL + t] : 0;
    __syncthreads();
    fillKV(0);

    float of[2][8][4];
    #pragma unroll
    for (int mi = 0; mi < 2; mi++)
        #pragma unroll
        for (int nf = 0; nf < 8; nf++)
            #pragma unroll
            for (int j = 0; j < 4; j++) of[mi][nf][j] = 0.f;
    float mA[2] = {-1e30f, -1e30f}, mB[2] = {-1e30f, -1e30f};
    float lA[2] = {0.f, 0.f},       lB[2] = {0.f, 0.f};

    for (int tt = 0; tt < ntiles; tt++) {
        int cur = tt & 1;
        int k0 = tt * 64;
        asm volatile("cp.async.wait_group 0;");
        if (tt + 1 < ntiles && t < 64) {
            int slot = (tt + 1) * 64 + t;
            krs[(1 - cur) * 64 + t] = (slot < cnt) ? idxp[b * LL + slot] : 0;
        }
        __syncthreads();
        if (tt + 1 < ntiles) fillKV(1 - cur);

        float sc[2][8][4];
        #pragma unroll
        for (int mi = 0; mi < 2; mi++)
            #pragma unroll
            for (int nf = 0; nf < 8; nf++)
                #pragma unroll
                for (int j = 0; j < 4; j++) sc[mi][nf][j] = 0.f;
        #pragma unroll
        for (int ks = 0; ks < 8; ks++)
            #pragma unroll
            for (int nf = 0; nf < 8; nf++) {
                unsigned b0 = Ks[cur][nf * 8 + r][ks * 8 + cc];
                unsigned b1 = Ks[cur][nf * 8 + r][ks * 8 + cc + 4];
                #pragma unroll
                for (int mi = 0; mi < 2; mi++)
                    mma_tf32(sc[mi][nf], qa[mi][ks][0], qa[mi][ks][1],
                             qa[mi][ks][2], qa[mi][ks][3], b0, b1);
            }

        #pragma unroll
        for (int mi = 0; mi < 2; mi++) {
            float rA = -1e30f, rB = -1e30f;
            #pragma unroll
            for (int nf = 0; nf < 8; nf++) {
                int key0 = k0 + nf * 8 + 2 * cc;
                bool u0 = key0 < cnt, u1 = key0 + 1 < cnt;
                sc[mi][nf][0] = u0 ? sc[mi][nf][0] : -1e10f;
                sc[mi][nf][1] = u1 ? sc[mi][nf][1] : -1e10f;
                sc[mi][nf][2] = u0 ? sc[mi][nf][2] : -1e10f;
                sc[mi][nf][3] = u1 ? sc[mi][nf][3] : -1e10f;
                rA = fmaxf(rA, fmaxf(sc[mi][nf][0], sc[mi][nf][1]));
                rB = fmaxf(rB, fmaxf(sc[mi][nf][2], sc[mi][nf][3]));
            }
            rA = fmaxf(rA, __shfl_xor_sync(0xffffffffu, rA, 1));
            rA = fmaxf(rA, __shfl_xor_sync(0xffffffffu, rA, 2));
            rB = fmaxf(rB, __shfl_xor_sync(0xffffffffu, rB, 1));
            rB = fmaxf(rB, __shfl_xor_sync(0xffffffffu, rB, 2));

            float mAn = fmaxf(mA[mi], rA), mBn = fmaxf(mB[mi], rB);
            float cA = __expf(mA[mi] - mAn), cB = __expf(mB[mi] - mBn);
            mA[mi] = mAn; mB[mi] = mBn;
            lA[mi] *= cA; lB[mi] *= cB;

            float sumA = 0.f, sumB = 0.f;
            #pragma unroll
            for (int nf = 0; nf < 8; nf++) {
                float p0 = __expf(sc[mi][nf][0] - mAn), p1 = __expf(sc[mi][nf][1] - mAn);
                float p2 = __expf(sc[mi][nf][2] - mBn), p3 = __expf(sc[mi][nf][3] - mBn);
                sumA += p0 + p1; sumB += p2 + p3;
                of[mi][nf][0] *= cA; of[mi][nf][1] *= cA;
                of[mi][nf][2] *= cB; of[mi][nf][3] *= cB;
                *reinterpret_cast<uint2*>(&Pw[mi * 16 + r][nf * 8 + 2 * cc]) =
                    make_uint2(f2tf32(p0), f2tf32(p1));
                *reinterpret_cast<uint2*>(&Pw[mi * 16 + 8 + r][nf * 8 + 2 * cc]) =
                    make_uint2(f2tf32(p2), f2tf32(p3));
            }
            sumA += __shfl_xor_sync(0xffffffffu, sumA, 1);
            sumA += __shfl_xor_sync(0xffffffffu, sumA, 2);
            sumB += __shfl_xor_sync(0xffffffffu, sumB, 1);
            sumB += __shfl_xor_sync(0xffffffffu, sumB, 2);
            lA[mi] += sumA; lB[mi] += sumB;
        }
        __syncwarp();

        #pragma unroll
        for (int ks = 0; ks < 8; ks++) {
            unsigned pa[2][4];
            #pragma unroll
            for (int mi = 0; mi < 2; mi++) {
                pa[mi][0] = Pw[mi * 16 + r][ks * 8 + cc];
                pa[mi][1] = Pw[mi * 16 + 8 + r][ks * 8 + cc];
                pa[mi][2] = Pw[mi * 16 + r][ks * 8 + cc + 4];
                pa[mi][3] = Pw[mi * 16 + 8 + r][ks * 8 + cc + 4];
            }
            #pragma unroll
            for (int nf = 0; nf < 8; nf++) {
                unsigned b0 = Vs[cur][ks * 8 + cc][nf * 8 + r];
                unsigned b1 = Vs[cur][ks * 8 + cc + 4][nf * 8 + r];
                #pragma unroll
                for (int mi = 0; mi < 2; mi++)
                    mma_tf32(of[mi][nf], pa[mi][0], pa[mi][1], pa[mi][2], pa[mi][3],
                             b0, b1);
            }
        }
    }

    // Normalize + store, K-PAIR-PERMUTED within each 8-col octet:
    // logical l -> position (l<4 ? 2l : 2l-7). Logical pair (2cc, 2cc+1)
    // lands at (pA, pA+2) with pA = cc<2 ? 4cc : 4cc-7.
    int pA = (cc < 2) ? 4 * cc : 4 * cc - 7;
    #pragma unroll
    for (int mi = 0; mi < 2; mi++) {
        float iA = 1.f / lA[mi], iB = 1.f / lB[mi];
        size_t rowA = (size_t)b * LL + q0 + w * 32 + mi * 16 + r;
        #pragma unroll
        for (int nf = 0; nf < 8; nf++) {
            int colb = h * HD + nf * 8;
            O[rowA * EE + colb + pA]           = f2tf32(of[mi][nf][0] * iA);
            O[rowA * EE + colb + pA + 2]       = f2tf32(of[mi][nf][1] * iA);
            O[(rowA + 8) * EE + colb + pA]     = f2tf32(of[mi][nf][2] * iB);
            O[(rowA + 8) * EE + colb + pA + 2] = f2tf32(of[mi][nf][3] * iB);
        }
    }
}

// ---------------------------------------------------------------------------
// Launch
// ---------------------------------------------------------------------------
extern "C" void kernel_launch(void* const* d_in, const int* in_sizes, int n_in,
                              void* d_out, int out_size) {
    const float* x    = (const float*)d_in[0];
    const int*   mask = (const int*)  d_in[1];
    const float* Wq   = (const float*)d_in[2];
    const float* bq   = (const float*)d_in[3];
    const float* Wk   = (const float*)d_in[4];
    const float* bk   = (const float*)d_in[5];
    const float* Wv   = (const float*)d_in[6];
    const float* bv   = (const float*)d_in[7];
    const float* Wo   = (const float*)d_in[8];
    const float* bo   = (const float*)d_in[9];
    float* out = (float*)d_out;

    unsigned *Qp, *Kp, *Vp, *Ap, *Xp, *Wp;
    int *idxp, *cntp;
    cudaGetSymbolAddress((void**)&Qp, g_Q);
    cudaGetSymbolAddress((void**)&Kp, g_K);
    cudaGetSymbolAddress((void**)&Vp, g_V);
    cudaGetSymbolAddress((void**)&Ap, g_A);
    cudaGetSymbolAddress((void**)&Xp, g_X);
    cudaGetSymbolAddress((void**)&Wp, g_Wc);
    cudaGetSymbolAddress((void**)&idxp, g_idx);
    cudaGetSymbolAddress((void**)&cntp, g_cnt);

    static int attr_set = 0;
    if (!attr_set) {
        cudaFuncSetAttribute(qkv_gemm_tc, cudaFuncAttributeMaxDynamicSharedMemorySize,
                             GEMM_SMEM);
        cudaFuncSetAttribute(ogemm_tc, cudaFuncAttributeMaxDynamicSharedMemorySize,
                             GEMM_SMEM);
        cudaFuncSetAttribute(attn_tc, cudaFuncAttributeMaxDynamicSharedMemorySize,
                             ATTN_SMEM);
        attr_set = 1;
    }

    const int n8x = MM * EE / 8;
    const int n8w = EE * EE / 8;
    conv_tf32_perm_kernel<<<(n8x + 255) / 256, 256>>>((const float4*)x, (uint4*)Xp, n8x);
    dim3 wgrid((n8w + 255) / 256, 4);
    conv_w4_perm_kernel<<<wgrid, 256>>>((const float4*)Wq, (const float4*)Wk,
                                        (const float4*)Wv, (const float4*)Wo,
                                        (uint4*)Wp, n8w);
    compact_mask_kernel<<<BB, 1024>>>(mask, idxp, cntp);

    dim3 qkv_grid(EE / 256, MM / 128, 3);   // (4, 64, 3)
    qkv_gemm_tc<<<qkv_grid, 256, GEMM_SMEM>>>(Xp, Wp, bq, bk, bv, Qp, Kp, Vp);

    dim3 attn_grid(LL / 128, HH, BB);       // (16, 16, 4)
    attn_tc<<<attn_grid, 128, ATTN_SMEM>>>(Qp, Kp, Vp, idxp, cntp, Ap);

    dim3 ogrid(EE / 256, MM / 128);         // (4, 64)
    ogemm_tc<<<ogrid, 256, GEMM_SMEM>>>(Ap, Wp + 3 * EE * EE, bo, out);
}

// round 15
// speedup vs baseline: 1.5196x; 1.5196x over previous
#include <cuda_runtime.h>

#define BB 4
#define LL 2048
#define EE 1024
#define HH 16
#define HD 64
#define MM (BB*LL)   // 8192

// Scratch (allocation-free), all tf32-encoded uints (natural layouts).
__device__ unsigned g_Q[MM*EE];
__device__ unsigned g_K[MM*EE];
__device__ unsigned g_V[MM*EE];
__device__ unsigned g_A[MM*EE];
__device__ unsigned g_X[MM*EE];
__device__ unsigned g_Wc[4*EE*EE];
__device__ int g_idx[BB*LL];
__device__ int g_cnt[BB];

__device__ __forceinline__ unsigned f2tf32(float v) {
    unsigned u;
    asm("cvt.rna.tf32.f32 %0, %1;" : "=r"(u) : "f"(v));
    return u;
}

__device__ __forceinline__ void mma_tf32(float* c,
    unsigned a0, unsigned a1, unsigned a2, unsigned a3,
    unsigned b0, unsigned b1) {
    asm volatile(
        "mma.sync.aligned.m16n8k8.row.col.f32.tf32.tf32.f32 "
        "{%0,%1,%2,%3}, {%4,%5,%6,%7}, {%8,%9}, {%0,%1,%2,%3};\n"
        : "+f"(c[0]), "+f"(c[1]), "+f"(c[2]), "+f"(c[3])
        : "r"(a0), "r"(a1), "r"(a2), "r"(a3), "r"(b0), "r"(b1));
}

__device__ __forceinline__ void cp16(void* dst_smem, const void* src) {
    unsigned d = (unsigned)__cvta_generic_to_shared(dst_smem);
    asm volatile("cp.async.cg.shared.global [%0], [%1], 16;" :: "r"(d), "l"(src));
}

// fp32 -> tf32 bulk conversion (x), natural layout
__global__ void conv_tf32_kernel(const float4* __restrict__ in,
                                 uint4* __restrict__ out, int n4) {
    int i = blockIdx.x * blockDim.x + threadIdx.x;
    if (i < n4) {
        float4 v = in[i];
        out[i] = make_uint4(f2tf32(v.x), f2tf32(v.y), f2tf32(v.z), f2tf32(v.w));
    }
}

// all 4 weights in one launch (grid.y selects weight), natural layout
__global__ void conv_w4_kernel(const float4* __restrict__ w0, const float4* __restrict__ w1,
                               const float4* __restrict__ w2, const float4* __restrict__ w3,
                               uint4* __restrict__ out, int n4w) {
    const float4* src = (blockIdx.y == 0) ? w0 : (blockIdx.y == 1) ? w1
                      : (blockIdx.y == 2) ? w2 : w3;
    int i = blockIdx.x * blockDim.x + threadIdx.x;
    if (i < n4w) {
        float4 v = src[i];
        out[(size_t)blockIdx.y * n4w + i] =
            make_uint4(f2tf32(v.x), f2tf32(v.y), f2tf32(v.z), f2tf32(v.w));
    }
}

// ---------------------------------------------------------------------------
// Per-batch mask compaction: idx[b][0..cnt) = pseudo-positions with mask!=0.
// ---------------------------------------------------------------------------
__global__ __launch_bounds__(1024) void compact_mask_kernel(
    const int* __restrict__ mask, int* __restrict__ idx, int* __restrict__ cnt)
{
    __shared__ int wsum[32];
    int b = blockIdx.x, t = threadIdx.x;
    int lane = t & 31, w = t >> 5;

    int v0 = mask[b * LL + 2 * t];
    int v1 = mask[b * LL + 2 * t + 1];
    int n = (v0 != 0) + (v1 != 0);

    int s = n;
    #pragma unroll
    for (int d = 1; d < 32; d <<= 1) {
        int x = __shfl_up_sync(0xffffffffu, s, d);
        if (lane >= d) s += x;
    }
    if (lane == 31) wsum[w] = s;
    __syncthreads();
    if (w == 0) {
        int x = wsum[lane];
        #pragma unroll
        for (int d = 1; d < 32; d <<= 1) {
            int y = __shfl_up_sync(0xffffffffu, x, d);
            if (lane >= d) x += y;
        }
        wsum[lane] = x;
    }
    __syncthreads();

    int base = (w > 0 ? wsum[w - 1] : 0) + (s - n);
    int p = base;
    if (v0) idx[b * LL + p++] = 2 * t;
    if (v1) idx[b * LL + p++] = 2 * t + 1;
    if (t == 1023) cnt[b] = wsum[31];
}

// ---------------------------------------------------------------------------
// Shared TF32 TC GEMM body: 128x256 CTA tile, BK=64, 8 warps (2m x 4n),
// warp tile 64x64, cp.async 2-stage. Scalar fragment loads (R11 layout),
// pad 68 (68 mod 32 = 4 -> bank 4r+cc, conflict-free). BK=64 halves the
// barrier/commit count vs BK=32.
// ---------------------------------------------------------------------------
#define GPAD 68
#define GS_A (128*GPAD)
#define GS_B (256*GPAD)
#define GEMM_SMEM ((2*GS_A + 2*GS_B) * 4)   // 208896 B

template <int STORE_TF32>
__device__ __forceinline__ void gemm_body(
    const unsigned* __restrict__ A, const unsigned* __restrict__ W,
    const float* __restrict__ bias, void* __restrict__ Cout,
    float oscale, int m0, int n0, unsigned* sm)
{
    unsigned* As = sm;
    unsigned* Bs = sm + 2 * GS_A;

    int tid = threadIdx.x;
    int w = tid >> 5, lane = tid & 31;
    int wm = (w & 1) * 64, wn = (w >> 1) * 64;
    int r = lane >> 2, cc = lane & 3;

    const unsigned* Abase = A + (size_t)m0 * EE;
    const unsigned* Wbase = W + (size_t)n0 * EE;

    float acc[4][8][4];
    #pragma unroll
    for (int mi = 0; mi < 4; mi++)
        #pragma unroll
        for (int ni = 0; ni < 8; ni++)
            #pragma unroll
            for (int j = 0; j < 4; j++) acc[mi][ni][j] = 0.f;

    auto fill = [&](int s, int k0) {
        #pragma unroll
        for (int i = 0; i < 8; i++) {            // A: 128 rows x 64 k = 2048 uint4
            int lin = tid + i * 256;
            int rr = lin >> 4, kc = (lin & 15) << 2;
            cp16(&As[s * GS_A + rr * GPAD + kc], Abase + (size_t)rr * EE + k0 + kc);
        }
        #pragma unroll
        for (int i = 0; i < 16; i++) {           // B: 256 rows x 64 k = 4096 uint4
            int lin = tid + i * 256;
            int rr = lin >> 4, kc = (lin & 15) << 2;
            cp16(&Bs[s * GS_B + rr * GPAD + kc], Wbase + (size_t)rr * EE + k0 + kc);
        }
        asm volatile("cp.async.commit_group;");
    };

    fill(0, 0);
    for (int it = 0; it < EE / 64; it++) {
        int cur = it & 1;
        if (it + 1 < EE / 64) {
            fill(1 - cur, (it + 1) * 64);
            asm volatile("cp.async.wait_group 1;");
        } else {
            asm volatile("cp.async.wait_group 0;");
        }
        __syncthreads();

        const unsigned* Ac = &As[cur * GS_A];
        const unsigned* Bc = &Bs[cur * GS_B];
        #pragma unroll
        for (int kk = 0; kk < 64; kk += 8) {
            unsigned af[4][4], bf[8][2];
            #pragma unroll
            for (int mi = 0; mi < 4; mi++) {
                int mb = wm + mi * 16;
                af[mi][0] = Ac[(mb + r) * GPAD + kk + cc];
                af[mi][1] = Ac[(mb + 8 + r) * GPAD + kk + cc];
                af[mi][2] = Ac[(mb + r) * GPAD + kk + cc + 4];
                af[mi][3] = Ac[(mb + 8 + r) * GPAD + kk + cc + 4];
            }
            #pragma unroll
            for (int ni = 0; ni < 8; ni++) {
                int nb = wn + ni * 8 + r;
                bf[ni][0] = Bc[nb * GPAD + kk + cc];
                bf[ni][1] = Bc[nb * GPAD + kk + cc + 4];
            }
            #pragma unroll
            for (int mi = 0; mi < 4; mi++)
                #pragma unroll
                for (int ni = 0; ni < 8; ni++)
                    mma_tf32(acc[mi][ni], af[mi][0], af[mi][1], af[mi][2], af[mi][3],
                             bf[ni][0], bf[ni][1]);
        }
        __syncthreads();
    }

    #pragma unroll
    for (int mi = 0; mi < 4; mi++) {
        int m = m0 + wm + mi * 16 + r;
        #pragma unroll
        for (int ni = 0; ni < 8; ni++) {
            int n = n0 + wn + ni * 8 + cc * 2;
            float2 bv = *reinterpret_cast<const float2*>(&bias[n]);
            float o0 = (acc[mi][ni][0] + bv.x) * oscale;
            float o1 = (acc[mi][ni][1] + bv.y) * oscale;
            float o2 = (acc[mi][ni][2] + bv.x) * oscale;
            float o3 = (acc[mi][ni][3] + bv.y) * oscale;
            if (STORE_TF32) {
                unsigned* C = (unsigned*)Cout;
                *reinterpret_cast<uint2*>(&C[(size_t)m * EE + n]) =
                    make_uint2(f2tf32(o0), f2tf32(o1));
                *reinterpret_cast<uint2*>(&C[(size_t)(m + 8) * EE + n]) =
                    make_uint2(f2tf32(o2), f2tf32(o3));
            } else {
                float* C = (float*)Cout;
                *reinterpret_cast<float2*>(&C[(size_t)m * EE + n]) = make_float2(o0, o1);
                *reinterpret_cast<float2*>(&C[(size_t)(m + 8) * EE + n]) = make_float2(o2, o3);
            }
        }
    }
}

// Fused Q/K/V projection: grid.z selects weight/bias/output/oscale.
__global__ __launch_bounds__(256) void qkv_gemm_tc(
    const unsigned* __restrict__ A, const unsigned* __restrict__ Wall,
    const float* __restrict__ bq, const float* __restrict__ bk,
    const float* __restrict__ bv,
    unsigned* __restrict__ Qo, unsigned* __restrict__ Ko, unsigned* __restrict__ Vo)
{
    extern __shared__ unsigned sm[];
    int z = blockIdx.z;
    const unsigned* W = Wall + (size_t)z * EE * EE;
    const float* bias = (z == 0) ? bq : (z == 1) ? bk : bv;
    unsigned* C = (z == 0) ? Qo : (z == 1) ? Ko : Vo;
    float oscale = (z == 0) ? 0.125f : 1.0f;
    gemm_body<1>(A, W, bias, C, oscale, blockIdx.y * 128, blockIdx.x * 256, sm);
}

// O-projection (fp32 output).
__global__ __launch_bounds__(256) void ogemm_tc(
    const unsigned* __restrict__ A, const unsigned* __restrict__ W,
    const float* __restrict__ bias, float* __restrict__ Cout)
{
    extern __shared__ unsigned sm[];
    gemm_body<0>(A, W, bias, Cout, 1.0f, blockIdx.y * 128, blockIdx.x * 256, sm);
}

// ---------------------------------------------------------------------------
// Tensor-core flash attention over compacted keys, double-buffered cp.async
// gather (R11 version, natural output layout).
// ---------------------------------------------------------------------------
#define ATTN_SMEM ((8704*3 + 128) * 4)   // 104960 B

__global__ __launch_bounds__(128) void attn_tc(
    const unsigned* __restrict__ Q, const unsigned* __restrict__ K,
    const unsigned* __restrict__ V, const int* __restrict__ idxp,
    const int* __restrict__ cntp, unsigned* __restrict__ O)
{
    extern __shared__ unsigned smn[];
    unsigned (*Ks)[64][68] = (unsigned (*)[64][68])smn;
    unsigned (*Vs)[64][68] = (unsigned (*)[64][68])(smn + 8704);
    unsigned (*Ps)[68] = (unsigned (*)[68])(smn + 17408);
    int* krs = (int*)(smn + 26112);

    int b = blockIdx.z, h = blockIdx.y;
    int q0 = blockIdx.x * 128;
    int t = threadIdx.x, w = t >> 5, lane = t & 31;
    int r = lane >> 2, cc = lane & 3;
    size_t hbase = ((size_t)(b * HH + h)) * LL * HD;
    unsigned (*Pw)[68] = &Ps[w * 32];

    int cnt = cntp[b];
    int ntiles = (cnt + 63) >> 6;

    auto fillKV = [&](int s) {
        #pragma unroll
        for (int i = 0; i < 8; i++) {
            int lin = t + i * 128;
            int row = lin >> 4, chunk = lin & 15, c = chunk << 2;
            int g = krs[s * 64 + row];
            size_t rb = hbase + (size_t)g * HD + c;
            cp16(&Ks[s][row][c], K + rb);
            cp16(&Vs[s][row][c], V + rb);
        }
        asm volatile("cp.async.commit_group;");
    };

    {
        const uint4* Qg = (const uint4*)(Q + hbase + (size_t)(q0 + w * 32) * HD);
        #pragma unroll
        for (int i = 0; i < 16; i++) {
            int lin = lane + i * 32;
            int row = lin >> 4, c = (lin & 15) << 2;
            *reinterpret_cast<uint4*>(&Pw[row][c]) = Qg[lin];
        }
    }
    __syncwarp();
    unsigned qa[2][8][4];
    #pragma unroll
    for (int mi = 0; mi < 2; mi++)
        #pragma unroll
        for (int ks = 0; ks < 8; ks++) {
            qa[mi][ks][0] = Pw[mi * 16 + r][ks * 8 + cc];
            qa[mi][ks][1] = Pw[mi * 16 + 8 + r][ks * 8 + cc];
            qa[mi][ks][2] = Pw[mi * 16 + r][ks * 8 + cc + 4];
            qa[mi][ks][3] = Pw[mi * 16 + 8 + r][ks * 8 + cc + 4];
        }

    if (t < 64) krs[t] = (t < cnt) ? idxp[b * LL + t] : 0;
    __syncthreads();
    fillKV(0);

    float of[2][8][4];
    #pragma unroll
    for (int mi = 0; mi < 2; mi++)
        #pragma unroll
        for (int nf = 0; nf < 8; nf++)
            #pragma unroll
            for (int j = 0; j < 4; j++) of[mi][nf][j] = 0.f;
    float mA[2] = {-1e30f, -1e30f}, mB[2] = {-1e30f, -1e30f};
    float lA[2] = {0.f, 0.f},       lB[2] = {0.f, 0.f};

    for (int tt = 0; tt < ntiles; tt++) {
        int cur = tt & 1;
        int k0 = tt * 64;
        asm volatile("cp.async.wait_group 0;");
        if (tt + 1 < ntiles && t < 64) {
            int slot = (tt + 1) * 64 + t;
            krs[(1 - cur) * 64 + t] = (slot < cnt) ? idxp[b * LL + slot] : 0;
        }
        __syncthreads();
        if (tt + 1 < ntiles) fillKV(1 - cur);

        float sc[2][8][4];
        #pragma unroll
        for (int mi = 0; mi < 2; mi++)
            #pragma unroll
            for (int nf = 0; nf < 8; nf++)
                #pragma unroll
                for (int j = 0; j < 4; j++) sc[mi][nf][j] = 0.f;
        #pragma unroll
        for (int ks = 0; ks < 8; ks++)
            #pragma unroll
            for (int nf = 0; nf < 8; nf++) {
                unsigned b0 = Ks[cur][nf * 8 + r][ks * 8 + cc];
                unsigned b1 = Ks[cur][nf * 8 + r][ks * 8 + cc + 4];
                #pragma unroll
                for (int mi = 0; mi < 2; mi++)
                    mma_tf32(sc[mi][nf], qa[mi][ks][0], qa[mi][ks][1],
                             qa[mi][ks][2], qa[mi][ks][3], b0, b1);
            }

        #pragma unroll
        for (int mi = 0; mi < 2; mi++) {
            float rA = -1e30f, rB = -1e30f;
            #pragma unroll
            for (int nf = 0; nf < 8; nf++) {
                int key0 = k0 + nf * 8 + 2 * cc;
                bool u0 = key0 < cnt, u1 = key0 + 1 < cnt;
                sc[mi][nf][0] = u0 ? sc[mi][nf][0] : -1e10f;
                sc[mi][nf][1] = u1 ? sc[mi][nf][1] : -1e10f;
                sc[mi][nf][2] = u0 ? sc[mi][nf][2] : -1e10f;
                sc[mi][nf][3] = u1 ? sc[mi][nf][3] : -1e10f;
                rA = fmaxf(rA, fmaxf(sc[mi][nf][0], sc[mi][nf][1]));
                rB = fmaxf(rB, fmaxf(sc[mi][nf][2], sc[mi][nf][3]));
            }
            rA = fmaxf(rA, __shfl_xor_sync(0xffffffffu, rA, 1));
            rA = fmaxf(rA, __shfl_xor_sync(0xffffffffu, rA, 2));
            rB = fmaxf(rB, __shfl_xor_sync(0xffffffffu, rB, 1));
            rB = fmaxf(rB, __shfl_xor_sync(0xffffffffu, rB, 2));

            float mAn = fmaxf(mA[mi], rA), mBn = fmaxf(mB[mi], rB);
            float cA = __expf(mA[mi] - mAn), cB = __expf(mB[mi] - mBn);
            mA[mi] = mAn; mB[mi] = mBn;
            lA[mi] *= cA; lB[mi] *= cB;

            float sumA = 0.f, sumB = 0.f;
            #pragma unroll
            for (int nf = 0; nf < 8; nf++) {
                float p0 = __expf(sc[mi][nf][0] - mAn), p1 = __expf(sc[mi][nf][1] - mAn);
                float p2 = __expf(sc[mi][nf][2] - mBn), p3 = __expf(sc[mi][nf][3] - mBn);
                sumA += p0 + p1; sumB += p2 + p3;
                of[mi][nf][0] *= cA; of[mi][nf][1] *= cA;
                of[mi][nf][2] *= cB; of[mi][nf][3] *= cB;
                *reinterpret_cast<uint2*>(&Pw[mi * 16 + r][nf * 8 + 2 * cc]) =
                    make_uint2(f2tf32(p0), f2tf32(p1));
                *reinterpret_cast<uint2*>(&Pw[mi * 16 + 8 + r][nf * 8 + 2 * cc]) =
                    make_uint2(f2tf32(p2), f2tf32(p3));
            }
            sumA += __shfl_xor_sync(0xffffffffu, sumA, 1);
            sumA += __shfl_xor_sync(0xffffffffu, sumA, 2);
            sumB += __shfl_xor_sync(0xffffffffu, sumB, 1);
            sumB += __shfl_xor_sync(0xffffffffu, sumB, 2);
            lA[mi] += sumA; lB[mi] += sumB;
        }
        __syncwarp();

        #pragma unroll
        for (int ks = 0; ks < 8; ks++) {
            unsigned pa[2][4];
            #pragma unroll
            for (int mi = 0; mi < 2; mi++) {
                pa[mi][0] = Pw[mi * 16 + r][ks * 8 + cc];
                pa[mi][1] = Pw[mi * 16 + 8 + r][ks * 8 + cc];
                pa[mi][2] = Pw[mi * 16 + r][ks * 8 + cc + 4];
                pa[mi][3] = Pw[mi * 16 + 8 + r][ks * 8 + cc + 4];
            }
            #pragma unroll
            for (int nf = 0; nf < 8; nf++) {
                unsigned b0 = Vs[cur][ks * 8 + cc][nf * 8 + r];
                unsigned b1 = Vs[cur][ks * 8 + cc + 4][nf * 8 + r];
                #pragma unroll
                for (int mi = 0; mi < 2; mi++)
                    mma_tf32(of[mi][nf], pa[mi][0], pa[mi][1], pa[mi][2], pa[mi][3],
                             b0, b1);
            }
        }
    }

    #pragma unroll
    for (int mi = 0; mi < 2; mi++) {
        float iA = 1.f / lA[mi], iB = 1.f / lB[mi];
        size_t rowA = (size_t)b * LL + q0 + w * 32 + mi * 16 + r;
        #pragma unroll
        for (int nf = 0; nf < 8; nf++) {
            int col = h * HD + nf * 8 + 2 * cc;
            *reinterpret_cast<uint2*>(&O[rowA * EE + col]) =
                make_uint2(f2tf32(of[mi][nf][0] * iA), f2tf32(of[mi][nf][1] * iA));
            *reinterpret_cast<uint2*>(&O[(rowA + 8) * EE + col]) =
                make_uint2(f2tf32(of[mi][nf][2] * iB), f2tf32(of[mi][nf][3] * iB));
        }
    }
}

// ---------------------------------------------------------------------------
// Launch
// ---------------------------------------------------------------------------
extern "C" void kernel_launch(void* const* d_in, const int* in_sizes, int n_in,
                              void* d_out, int out_size) {
    const float* x    = (const float*)d_in[0];
    const int*   mask = (const int*)  d_in[1];
    const float* Wq   = (const float*)d_in[2];
    const float* bq   = (const float*)d_in[3];
    const float* Wk   = (const float*)d_in[4];
    const float* bk   = (const float*)d_in[5];
    const float* Wv   = (const float*)d_in[6];
    const float* bv   = (const float*)d_in[7];
    const float* Wo   = (const float*)d_in[8];
    const float* bo   = (const float*)d_in[9];
    float* out = (float*)d_out;

    unsigned *Qp, *Kp, *Vp, *Ap, *Xp, *Wp;
    int *idxp, *cntp;
    cudaGetSymbolAddress((void**)&Qp, g_Q);
    cudaGetSymbolAddress((void**)&Kp, g_K);
    cudaGetSymbolAddress((void**)&Vp, g_V);
    cudaGetSymbolAddress((void**)&Ap, g_A);
    cudaGetSymbolAddress((void**)&Xp, g_X);
    cudaGetSymbolAddress((void**)&Wp, g_Wc);
    cudaGetSymbolAddress((void**)&idxp, g_idx);
    cudaGetSymbolAddress((void**)&cntp, g_cnt);

    static int attr_set = 0;
    if (!attr_set) {
        cudaFuncSetAttribute(qkv_gemm_tc, cudaFuncAttributeMaxDynamicSharedMemorySize,
                             GEMM_SMEM);
        cudaFuncSetAttribute(ogemm_tc, cudaFuncAttributeMaxDynamicSharedMemorySize,
                             GEMM_SMEM);
        cudaFuncSetAttribute(attn_tc, cudaFuncAttributeMaxDynamicSharedMemorySize,
                             ATTN_SMEM);
        attr_set = 1;
    }

    const int n4x = MM * EE / 4;
    const int n4w = EE * EE / 4;
    conv_tf32_kernel<<<(n4x + 255) / 256, 256>>>((const float4*)x, (uint4*)Xp, n4x);
    dim3 wgrid((n4w + 255) / 256, 4);
    conv_w4_kernel<<<wgrid, 256>>>((const float4*)Wq, (const float4*)Wk,
                                   (const float4*)Wv, (const float4*)Wo,
                                   (uint4*)Wp, n4w);
    compact_mask_kernel<<<BB, 1024>>>(mask, idxp, cntp);

    dim3 qkv_grid(EE / 256, MM / 128, 3);   // (4, 64, 3)
    qkv_gemm_tc<<<qkv_grid, 256, GEMM_SMEM>>>(Xp, Wp, bq, bk, bv, Qp, Kp, Vp);

    dim3 attn_grid(LL / 128, HH, BB);       // (16, 16, 4)
    attn_tc<<<attn_grid, 128, ATTN_SMEM>>>(Qp, Kp, Vp, idxp, cntp, Ap);

    dim3 ogrid(EE / 256, MM / 128);         // (4, 64)
    ogemm_tc<<<ogrid, 256, GEMM_SMEM>>>(Ap, Wp + 3 * EE * EE, bo, out);
}